// round 1
// baseline (speedup 1.0000x reference)
#include <cuda_runtime.h>
#include <cstdint>

#define DIM        2048
#define NEXP       8
#define TILE_T     32          // tokens per block (one per lane)
#define WARPS      8
#define THREADS    (WARPS * 32)
#define COLS_PER_WARP (DIM / WARPS)   // 256
#define STAGE_COLS 16
#define NSTAGES    (COLS_PER_WARP / STAGE_COLS)  // 16
#define NBUF       2
#define CHUNKS     (STAGE_COLS / 4)   // 4 float4 per row per stage
#define BUF_F4     (TILE_T * CHUNKS)  // 128 float4 per buffer
#define MOE_COEFF  0.01f

__device__ float        g_imp[NEXP];
__device__ unsigned int g_load[NEXP];

__device__ __forceinline__ unsigned long long ffma2(unsigned long long a,
                                                    unsigned long long b,
                                                    unsigned long long c) {
    unsigned long long d;
    asm("fma.rn.f32x2 %0, %1, %2, %3;" : "=l"(d) : "l"(a), "l"(b), "l"(c));
    return d;
}
__device__ __forceinline__ unsigned long long pack2(float x, float y) {
    unsigned long long d;
    asm("mov.b64 %0, {%1, %2};" : "=l"(d) : "f"(x), "f"(y));
    return d;
}
__device__ __forceinline__ float2 unpack2(unsigned long long d) {
    float2 r;
    asm("mov.b64 {%0, %1}, %2;" : "=f"(r.x), "=f"(r.y) : "l"(d));
    return r;
}

__global__ void zero_stats_kernel() {
    int t = threadIdx.x;
    if (t < NEXP) { g_imp[t] = 0.0f; g_load[t] = 0u; }
}

__global__ void __launch_bounds__(THREADS)
gate_kernel(const float* __restrict__ x, const float* __restrict__ W,
            float* __restrict__ out, int half) {
    extern __shared__ float4 smem[];
    // layout: [8 warps][NBUF][32 rows][4 chunks] float4 = 32768 B, then logits
    float* logitsBuf = reinterpret_cast<float*>(smem + WARPS * NBUF * BUF_F4);

    const int tid  = threadIdx.x;
    const int w    = tid >> 5;
    const int lane = tid & 31;
    const int tok0 = blockIdx.x * TILE_T;
    const int colBase = w * COLS_PER_WARP;
    float4* xb = smem + w * (NBUF * BUF_F4);

    const int c_st  = lane & 3;      // staging chunk
    const int r0_st = lane >> 2;     // staging base row

    // ---- issue one stage of cp.async (2 KB: 32 rows x 16 cols) ----
    #define ISSUE_STAGE(s)                                                      \
    {                                                                           \
        int bi_ = (s) & (NBUF - 1);                                             \
        const float* src0_ = x + (size_t)(tok0 + r0_st) * DIM                   \
                               + colBase + (s) * STAGE_COLS + c_st * 4;         \
        _Pragma("unroll")                                                       \
        for (int j = 0; j < 4; j++) {                                           \
            int r_ = r0_st + j * 8;                                             \
            const float* src_ = src0_ + (size_t)j * 8 * DIM;                    \
            float4* dst_ = xb + bi_ * BUF_F4 + r_ * CHUNKS                      \
                              + (c_st ^ ((r_ >> 1) & 3));                       \
            unsigned int da_ = (unsigned int)__cvta_generic_to_shared(dst_);    \
            asm volatile("cp.async.cg.shared.global [%0], [%1], 16;"            \
                         :: "r"(da_), "l"(src_));                               \
        }                                                                       \
        asm volatile("cp.async.commit_group;");                                 \
    }

    unsigned long long acc[NEXP];
    #pragma unroll
    for (int e = 0; e < NEXP; e++) acc[e] = 0ULL;

    ISSUE_STAGE(0);
    ISSUE_STAGE(1);

    const float4* W4 = reinterpret_cast<const float4*>(W);
    const int swz = (lane >> 1) & 3;

    #pragma unroll 1
    for (int s = 0; s < NSTAGES; s++) {
        asm volatile("cp.async.wait_group 1;");
        __syncwarp();
        const int bi = s & (NBUF - 1);
        const float4* xs = xb + bi * BUF_F4 + lane * CHUNKS;
        const int wcol = (colBase + s * STAGE_COLS) >> 2;   // float4 index
        #pragma unroll
        for (int i = 0; i < CHUNKS; i++) {
            float4 xv = xs[i ^ swz];
            unsigned long long xlo = pack2(xv.x, xv.y);
            unsigned long long xhi = pack2(xv.z, xv.w);
            #pragma unroll
            for (int e = 0; e < NEXP; e++) {
                float4 wv = __ldg(&W4[e * (DIM / 4) + wcol + i]);
                acc[e] = ffma2(xlo, pack2(wv.x, wv.y), acc[e]);
                acc[e] = ffma2(xhi, pack2(wv.z, wv.w), acc[e]);
            }
        }
        __syncwarp();
        if (s + NBUF < NSTAGES) {
            ISSUE_STAGE(s + NBUF);
        } else {
            asm volatile("cp.async.commit_group;");
        }
    }

    // per-lane partial logits -> smem (row stride 9 words: conflict-free)
    float* lrow = logitsBuf + (w * TILE_T + lane) * 9;
    #pragma unroll
    for (int e = 0; e < NEXP; e++) {
        float2 t = unpack2(acc[e]);
        lrow[e] = t.x + t.y;
    }
    __syncthreads();

    if (w == 0) {
        // lane = token within tile; sum the 8 column-strip partials
        float lg[NEXP];
        #pragma unroll
        for (int e = 0; e < NEXP; e++) {
            float sum = 0.0f;
            #pragma unroll
            for (int ww = 0; ww < WARPS; ww++)
                sum += logitsBuf[(ww * TILE_T + lane) * 9 + e];
            lg[e] = sum;
        }
        // softmax over 8
        float m = lg[0];
        #pragma unroll
        for (int e = 1; e < NEXP; e++) m = fmaxf(m, lg[e]);
        float p[NEXP], psum = 0.0f;
        #pragma unroll
        for (int e = 0; e < NEXP; e++) { p[e] = __expf(lg[e] - m); psum += p[e]; }
        float inv = 1.0f / psum;
        #pragma unroll
        for (int e = 0; e < NEXP; e++) p[e] *= inv;

        // top-1 (first max wins, matches jax argmax/top_k tie rule)
        int e0 = 0; float v0 = p[0];
        #pragma unroll
        for (int e = 1; e < NEXP; e++) if (p[e] > v0) { v0 = p[e]; e0 = e; }
        // top-2
        int e1 = (e0 == 0) ? 1 : 0; float v1 = p[e1];
        #pragma unroll
        for (int e = 0; e < NEXP; e++)
            if (e != e0 && p[e] > v1) { v1 = p[e]; e1 = e; }

        float rs = 1.0f / (v0 + v1);
        const int tok = tok0 + lane;
        out[tok * 2 + 0] = v0 * rs;
        out[tok * 2 + 1] = v1 * rs;
        out[half + tok * 2 + 0] = (float)e0;
        out[half + tok * 2 + 1] = (float)e1;

        // aux-loss statistics
        #pragma unroll
        for (int e = 0; e < NEXP; e++) {
            float v = p[e];
            #pragma unroll
            for (int o = 16; o; o >>= 1) v += __shfl_xor_sync(0xffffffffu, v, o);
            unsigned bal = __ballot_sync(0xffffffffu, e0 == e);
            if (lane == 0) {
                atomicAdd(&g_imp[e], v);
                atomicAdd(&g_load[e], (unsigned)__popc(bal));
            }
        }
    }
}

__global__ void finalize_kernel(float* __restrict__ out, int pos, float invN) {
    float s = 0.0f;
    #pragma unroll
    for (int e = 0; e < NEXP; e++)
        s += (g_imp[e] * invN) * ((float)g_load[e] * invN);
    out[pos] = (float)NEXP * s * MOE_COEFF;
}

extern "C" void kernel_launch(void* const* d_in, const int* in_sizes, int n_in,
                              void* d_out, int out_size) {
    const float* x = (const float*)d_in[0];
    const float* W = (const float*)d_in[1];
    float* out = (float*)d_out;

    const int ntok = in_sizes[0] / DIM;          // 16384
    const int half = (out_size - 1) / 2;         // 32768
    const int grid = ntok / TILE_T;              // 512
    const int smemB = WARPS * NBUF * BUF_F4 * 16 + WARPS * TILE_T * 9 * 4; // 41984

    zero_stats_kernel<<<1, 32>>>();
    gate_kernel<<<grid, THREADS, smemB>>>(x, W, out, half);
    finalize_kernel<<<1, 1>>>(out, out_size - 1, 1.0f / (float)ntok);
}

// round 2
// speedup vs baseline: 1.2332x; 1.2332x over previous
#include <cuda_runtime.h>
#include <cstdint>

#define DIM        2048
#define NEXP       8
#define TILE_T     64          // tokens per block (2 per lane)
#define WARPS      8
#define THREADS    (WARPS * 32)
#define COLS_PER_WARP (DIM / WARPS)   // 256
#define STAGE_COLS 16
#define NSTAGES    (COLS_PER_WARP / STAGE_COLS)  // 16
#define NBUF       2
#define CHUNKS     (STAGE_COLS / 4)   // 4 float4 per row per stage
#define BUF_F4     (TILE_T * CHUNKS)  // 256 float4 per buffer (4 KB)
#define MOE_COEFF  0.01f
#define MAX_BLOCKS 1024

__device__ float        g_imp_part[MAX_BLOCKS * NEXP];
__device__ float        g_load_part[MAX_BLOCKS * NEXP];
__device__ unsigned int g_ticket = 0;

__device__ __forceinline__ unsigned long long ffma2(unsigned long long a,
                                                    unsigned long long b,
                                                    unsigned long long c) {
    unsigned long long d;
    asm("fma.rn.f32x2 %0, %1, %2, %3;" : "=l"(d) : "l"(a), "l"(b), "l"(c));
    return d;
}
__device__ __forceinline__ unsigned long long pack2(float x, float y) {
    unsigned long long d;
    asm("mov.b64 %0, {%1, %2};" : "=l"(d) : "f"(x), "f"(y));
    return d;
}
__device__ __forceinline__ float2 unpack2(unsigned long long d) {
    float2 r;
    asm("mov.b64 {%0, %1}, %2;" : "=f"(r.x), "=f"(r.y) : "l"(d));
    return r;
}

__global__ void __launch_bounds__(THREADS)
gate_kernel(const float* __restrict__ x, const float* __restrict__ W,
            float* __restrict__ out, int half, int ntok, int auxPos) {
    extern __shared__ float4 smem[];
    // x staging: [8 warps][NBUF][64 rows][4 chunks] float4 = 64 KB.
    // logits buffer is UNIONED over the same smem (used only after compute).
    float* logitsBuf = reinterpret_cast<float*>(smem);

    const int tid  = threadIdx.x;
    const int w    = tid >> 5;
    const int lane = tid & 31;
    const int tok0 = blockIdx.x * TILE_T;
    const int colBase = w * COLS_PER_WARP;
    float4* xb = smem + w * (NBUF * BUF_F4);

    const int c_st  = lane & 3;      // staging chunk
    const int r0_st = lane >> 2;     // staging base row (0..7)

    // ---- issue one stage of cp.async (4 KB: 64 rows x 16 cols) ----
    #define ISSUE_STAGE(s)                                                      \
    {                                                                           \
        int bi_ = (s) & (NBUF - 1);                                             \
        const float* src0_ = x + (size_t)(tok0 + r0_st) * DIM                   \
                               + colBase + (s) * STAGE_COLS + c_st * 4;         \
        _Pragma("unroll")                                                       \
        for (int j = 0; j < 8; j++) {                                           \
            int r_ = r0_st + j * 8;                                             \
            const float* src_ = src0_ + (size_t)j * 8 * DIM;                    \
            float4* dst_ = xb + bi_ * BUF_F4 + r_ * CHUNKS                      \
                              + (c_st ^ ((r_ >> 1) & 3));                       \
            unsigned int da_ = (unsigned int)__cvta_generic_to_shared(dst_);    \
            asm volatile("cp.async.cg.shared.global [%0], [%1], 16;"            \
                         :: "r"(da_), "l"(src_));                               \
        }                                                                       \
        asm volatile("cp.async.commit_group;");                                 \
    }

    unsigned long long accA[NEXP], accB[NEXP];
    #pragma unroll
    for (int e = 0; e < NEXP; e++) { accA[e] = 0ULL; accB[e] = 0ULL; }

    ISSUE_STAGE(0);
    ISSUE_STAGE(1);

    const float4* W4 = reinterpret_cast<const float4*>(W);
    const int swz = (lane >> 1) & 3;   // same swizzle for rows lane and lane+32

    #pragma unroll 1
    for (int s = 0; s < NSTAGES; s++) {
        asm volatile("cp.async.wait_group 1;");
        __syncwarp();
        const int bi = s & (NBUF - 1);
        const float4* xsA = xb + bi * BUF_F4 + lane * CHUNKS;
        const float4* xsB = xb + bi * BUF_F4 + (lane + 32) * CHUNKS;
        const int wcol = (colBase + s * STAGE_COLS) >> 2;   // float4 index
        #pragma unroll
        for (int i = 0; i < CHUNKS; i++) {
            float4 xvA = xsA[i ^ swz];
            float4 xvB = xsB[i ^ swz];
            unsigned long long aLo = pack2(xvA.x, xvA.y);
            unsigned long long aHi = pack2(xvA.z, xvA.w);
            unsigned long long bLo = pack2(xvB.x, xvB.y);
            unsigned long long bHi = pack2(xvB.z, xvB.w);
            #pragma unroll
            for (int e = 0; e < NEXP; e++) {
                float4 wv = __ldg(&W4[e * (DIM / 4) + wcol + i]);
                unsigned long long wLo = pack2(wv.x, wv.y);
                unsigned long long wHi = pack2(wv.z, wv.w);
                accA[e] = ffma2(aLo, wLo, accA[e]);
                accA[e] = ffma2(aHi, wHi, accA[e]);
                accB[e] = ffma2(bLo, wLo, accB[e]);
                accB[e] = ffma2(bHi, wHi, accB[e]);
            }
        }
        __syncwarp();
        if (s + NBUF < NSTAGES) {
            ISSUE_STAGE(s + NBUF);
        } else {
            asm volatile("cp.async.commit_group;");
        }
    }

    // Finish pending cp.async, then reuse staging smem for logits.
    asm volatile("cp.async.wait_group 0;");
    __syncthreads();

    // per-lane partial logits -> smem (row stride 9 words: conflict-free)
    {
        float* lrowA = logitsBuf + (w * TILE_T + lane) * 9;
        float* lrowB = logitsBuf + (w * TILE_T + lane + 32) * 9;
        #pragma unroll
        for (int e = 0; e < NEXP; e++) {
            float2 tA = unpack2(accA[e]);
            float2 tB = unpack2(accB[e]);
            lrowA[e] = tA.x + tA.y;
            lrowB[e] = tB.x + tB.y;
        }
    }
    __syncthreads();

    if (w == 0) {
        float impLoc[NEXP];
        #pragma unroll
        for (int e = 0; e < NEXP; e++) impLoc[e] = 0.0f;
        int top1[2];

        #pragma unroll
        for (int half_t = 0; half_t < 2; half_t++) {
            const int tloc = lane + half_t * 32;
            float lg[NEXP];
            #pragma unroll
            for (int e = 0; e < NEXP; e++) {
                float sum = 0.0f;
                #pragma unroll
                for (int ww = 0; ww < WARPS; ww++)
                    sum += logitsBuf[(ww * TILE_T + tloc) * 9 + e];
                lg[e] = sum;
            }
            float m = lg[0];
            #pragma unroll
            for (int e = 1; e < NEXP; e++) m = fmaxf(m, lg[e]);
            float p[NEXP], psum = 0.0f;
            #pragma unroll
            for (int e = 0; e < NEXP; e++) { p[e] = __expf(lg[e] - m); psum += p[e]; }
            float inv = 1.0f / psum;
            #pragma unroll
            for (int e = 0; e < NEXP; e++) { p[e] *= inv; impLoc[e] += p[e]; }

            // top-1 / top-2 (first max wins: matches jax tie rule)
            int e0 = 0; float v0 = p[0];
            #pragma unroll
            for (int e = 1; e < NEXP; e++) if (p[e] > v0) { v0 = p[e]; e0 = e; }
            int e1 = (e0 == 0) ? 1 : 0; float v1 = p[e1];
            #pragma unroll
            for (int e = 0; e < NEXP; e++)
                if (e != e0 && p[e] > v1) { v1 = p[e]; e1 = e; }
            top1[half_t] = e0;

            float rs = 1.0f / (v0 + v1);
            const int tok = tok0 + tloc;
            out[tok * 2 + 0] = v0 * rs;
            out[tok * 2 + 1] = v1 * rs;
            out[half + tok * 2 + 0] = (float)e0;
            out[half + tok * 2 + 1] = (float)e1;
        }

        // per-block aux statistics -> scratch (no atomics, no pre-zero kernel)
        #pragma unroll
        for (int e = 0; e < NEXP; e++) {
            float v = impLoc[e];
            #pragma unroll
            for (int o = 16; o; o >>= 1) v += __shfl_xor_sync(0xffffffffu, v, o);
            unsigned bal0 = __ballot_sync(0xffffffffu, top1[0] == e);
            unsigned bal1 = __ballot_sync(0xffffffffu, top1[1] == e);
            if (lane == 0) {
                g_imp_part[blockIdx.x * NEXP + e]  = v;
                g_load_part[blockIdx.x * NEXP + e] = (float)(__popc(bal0) + __popc(bal1));
            }
        }
        __threadfence();

        // last-block finalize (deterministic; ticket resets itself each run)
        unsigned old = 0;
        if (lane == 0) old = atomicAdd(&g_ticket, 1u);
        old = __shfl_sync(0xffffffffu, old, 0);
        if (old == gridDim.x - 1) {
            __threadfence();
            const int e = lane & 7;
            const int q = lane >> 3;            // quarter of blocks
            const int nblk = gridDim.x;
            const int per = nblk / 4;
            float si = 0.0f, sl = 0.0f;
            for (int b = q * per; b < (q + 1) * per; b++) {
                si += __ldcg(&g_imp_part[b * NEXP + e]);
                sl += __ldcg(&g_load_part[b * NEXP + e]);
            }
            // combine quarters (lanes e, e+8, e+16, e+24)
            si += __shfl_xor_sync(0xffffffffu, si, 8);
            si += __shfl_xor_sync(0xffffffffu, si, 16);
            sl += __shfl_xor_sync(0xffffffffu, sl, 8);
            sl += __shfl_xor_sync(0xffffffffu, sl, 16);
            float invN = 1.0f / (float)ntok;
            float prod = (si * invN) * (sl * invN);
            // sum products over 8 experts (lanes 0..7)
            prod += __shfl_xor_sync(0xffffffffu, prod, 1);
            prod += __shfl_xor_sync(0xffffffffu, prod, 2);
            prod += __shfl_xor_sync(0xffffffffu, prod, 4);
            if (lane == 0) {
                out[auxPos] = (float)NEXP * prod * MOE_COEFF;
                g_ticket = 0;   // reset for next graph replay
            }
        }
    }
}

extern "C" void kernel_launch(void* const* d_in, const int* in_sizes, int n_in,
                              void* d_out, int out_size) {
    const float* x = (const float*)d_in[0];
    const float* W = (const float*)d_in[1];
    float* out = (float*)d_out;

    const int ntok = in_sizes[0] / DIM;          // 16384
    const int half = (out_size - 1) / 2;         // 32768
    const int grid = ntok / TILE_T;              // 256
    const int smemB = WARPS * NBUF * BUF_F4 * 16; // 65536 (logits unioned inside)

    static bool attrDone = false;
    if (!attrDone) {
        cudaFuncSetAttribute(gate_kernel,
                             cudaFuncAttributeMaxDynamicSharedMemorySize, smemB);
        attrDone = true;
    }

    gate_kernel<<<grid, THREADS, smemB>>>(x, W, out, half, ntok, out_size - 1);
}